// round 4
// baseline (speedup 1.0000x reference)
#include <cuda_runtime.h>
#include <math.h>

// ---------------- problem constants ----------------
#define BB   4
#define CX   256
#define HX   32
#define HY   65
#define NPIX (HY*HY)   // 4225
#define CG   128
#define KD   32
#define NBHW 16900.0f
#define EPSB 1e-5f
#define JOBS (17*HY)   // 17 row-strips of 4 x 65 cols = 1105

typedef unsigned long long ull;

// ---------------- packed f32x2 helpers ----------------
__device__ __forceinline__ ull pack2(float a, float b) {
    ull r; asm("mov.b64 %0, {%1,%2};" : "=l"(r) : "f"(a), "f"(b)); return r;
}
__device__ __forceinline__ ull bcast2(float a) { return pack2(a, a); }
__device__ __forceinline__ void unpack2(ull v, float& a, float& b) {
    asm("mov.b64 {%0,%1}, %2;" : "=f"(a), "=f"(b) : "l"(v));
}
__device__ __forceinline__ ull fma2(ull a, ull b, ull c) {
    ull d; asm("fma.rn.f32x2 %0, %1, %2, %3;" : "=l"(d) : "l"(a), "l"(b), "l"(c)); return d;
}

// ---------------- scratch ----------------
__device__ float g_h  [BB*CX*NPIX];
__device__ float g_tmp[BB*CG*NPIX];
__device__ float g_a  [BB*CG*NPIX];
__device__ float g_xu [BB*CG*NPIX];
__device__ float g_k  [BB*KD*NPIX];
__device__ float g_g  [BB*CG*NPIX];
__device__ float g_o1 [BB*CG*NPIX];
__device__ float g_stats[4*2*CG];

__global__ void zero_stats_kernel() {
    int i = threadIdx.x + blockIdx.x * blockDim.x;
    if (i < 4*2*CG) g_stats[i] = 0.f;
}

// =====================================================================
// conv3x3 v2: thread = 4 vertical pixels x 8 output channels.
// 18 LDG + 20 LDS.128 per ci for 144 fma2.
// =====================================================================
template<int CIN, bool HAS_BIAS, bool DO_STATS, bool DO_RELU>
__global__ void __launch_bounds__(256, 2) conv3x3_v2(
    const float* __restrict__ in, const float* __restrict__ W,
    const float* __restrict__ bias, float* __restrict__ out,
    float* __restrict__ stats, int Cout)
{
    const int b   = blockIdx.z;
    const int co0 = blockIdx.y * 8;
    const int tid = threadIdx.x;
    const int j   = blockIdx.x * 256 + tid;
    const bool jv = j < JOBS;
    const int s   = jv ? j / HY : 0;
    const int c   = jv ? j % HY : 0;
    const int r0  = s * 4;

    // row/col predicates for the 6 input rows (r0-1 .. r0+4) and 3 cols
    bool rv[6];
    #pragma unroll
    for (int rr = 0; rr < 6; rr++) {
        int row = r0 - 1 + rr;
        rv[rr] = jv && row >= 0 && row < HY;
    }
    const bool cl = c > 0, cr = c < HY - 1;

    // weights in smem: [ci(32)][copair(4)][tap(10 pad)] ull = 10 KB
    __shared__ __align__(16) ull sw[32 * 4 * 10];

    ull acc[16];   // [px(4)][copair(4)]
    #pragma unroll
    for (int i = 0; i < 16; i++) acc[i] = 0ull;

    const float* inb = in + (size_t)b * CIN * NPIX;

    for (int cc = 0; cc < CIN; cc += 32) {
        __syncthreads();
        for (int i = tid; i < 8 * 32 * 9; i += 256) {
            int co = i / 288;
            int rem = i % 288;
            int ci = rem / 9, t = rem % 9;
            ((float*)sw)[(((ci * 4 + (co >> 1)) * 10 + t) << 1) + (co & 1)] =
                W[((size_t)(co0 + co) * CIN + cc + ci) * 9 + t];
        }
        __syncthreads();

        #pragma unroll 1
        for (int ci = 0; ci < 32; ci++) {
            const float* pl = inb + (size_t)(cc + ci) * NPIX + (r0 - 1) * HY + c;
            ull inp[6][3];
            #pragma unroll
            for (int rr = 0; rr < 6; rr++) {
                const float* pr = pl + rr * HY;
                float v0 = (rv[rr] && cl) ? __ldg(pr - 1) : 0.f;
                float v1 =  rv[rr]        ? __ldg(pr)     : 0.f;
                float v2 = (rv[rr] && cr) ? __ldg(pr + 1) : 0.f;
                inp[rr][0] = bcast2(v0);
                inp[rr][1] = bcast2(v1);
                inp[rr][2] = bcast2(v2);
            }
            const ulonglong2* wq = (const ulonglong2*)(sw + ci * 40);
            #pragma unroll
            for (int cop = 0; cop < 4; cop++) {
                ulonglong2 q0 = wq[cop*5+0], q1 = wq[cop*5+1], q2 = wq[cop*5+2],
                           q3 = wq[cop*5+3], q4 = wq[cop*5+4];
                ull w[9] = {q0.x, q0.y, q1.x, q1.y, q2.x, q2.y, q3.x, q3.y, q4.x};
                #pragma unroll
                for (int px = 0; px < 4; px++) {
                    ull a = acc[px*4 + cop];
                    #pragma unroll
                    for (int t = 0; t < 9; t++)
                        a = fma2(w[t], inp[px + t/3][t%3], a);
                    acc[px*4 + cop] = a;
                }
            }
        }
    }

    // -------- epilogue --------
    #pragma unroll
    for (int cop = 0; cop < 4; cop++) {
        int coA = co0 + 2*cop, coB = coA + 1;
        float bA = HAS_BIAS ? __ldg(bias + coA) : 0.f;
        float bB = HAS_BIAS ? __ldg(bias + coB) : 0.f;
        float sA = 0.f, qA = 0.f, sB = 0.f, qB = 0.f;
        #pragma unroll
        for (int px = 0; px < 4; px++) {
            float vA, vB;
            unpack2(acc[px*4 + cop], vA, vB);
            bool pv = jv && (r0 + px) < HY;
            if (!pv) { vA = 0.f; vB = 0.f; }
            if (DO_STATS) { sA += vA; qA += vA*vA; sB += vB; qB += vB*vB; }
            if (pv) {
                int p = (r0 + px) * HY + c;
                float oA = vA + bA, oB = vB + bB;
                if (DO_RELU) { oA = fmaxf(oA, 0.f); oB = fmaxf(oB, 0.f); }
                out[((size_t)b * Cout + coA) * NPIX + p] = oA;
                out[((size_t)b * Cout + coB) * NPIX + p] = oB;
            }
        }
        if (DO_STATS) {
            #pragma unroll
            for (int o = 16; o > 0; o >>= 1) {
                sA += __shfl_down_sync(0xffffffffu, sA, o);
                qA += __shfl_down_sync(0xffffffffu, qA, o);
                sB += __shfl_down_sync(0xffffffffu, sB, o);
                qB += __shfl_down_sync(0xffffffffu, qB, o);
            }
            if ((tid & 31) == 0) {
                atomicAdd(&stats[2*coA],     sA);
                atomicAdd(&stats[2*coA + 1], qA);
                atomicAdd(&stats[2*coB],     sB);
                atomicAdd(&stats[2*coB + 1], qB);
            }
        }
    }
}

// =====================================================================
// ConvTranspose: all 4 parity classes in ONE kernel (z = b*4 + class).
//   out[b,co,2*iy+kh, 2*ix+kw] += x[b,ci,iy,ix] * Wt[co,ci,kh,kw]
// =====================================================================
template<int NTH, int NTW>
__device__ __forceinline__ void convt_body(
    const float* __restrict__ x, const float* __restrict__ Wt,
    const float* __restrict__ bt, ull* swt, int b, int co0, int bx, int tid)
{
    constexpr int NT  = NTH * NTW;
    constexpr int PY  = (NTH == 2) ? 0 : 1;
    constexpr int PXP = (NTW == 2) ? 0 : 1;
    constexpr int CXN = (PXP == 0) ? 33 : 32;
    constexpr int RY  = (PY  == 0) ? 33 : 32;
    constexpr int NPC = RY * CXN;

    if (bx * 256 >= (NPC + 1) / 2) return;   // block-uniform

    const int pair = bx * 256 + tid;
    const int p0 = pair*2, p1 = p0 + 1;
    const bool v0 = p0 < NPC, v1 = p1 < NPC;
    const int cr0 = v0 ? p0 / CXN : 0, cc0_ = v0 ? p0 % CXN : 0;
    const int cr1 = v1 ? p1 / CXN : 0, cc1_ = v1 ? p1 % CXN : 0;

    bool ok0[NT], ok1[NT];
    int  io0[NT], io1[NT];
    #pragma unroll
    for (int tt = 0; tt < NT; tt++) {
        int th = tt / NTW, tw = tt % NTW;
        int iy0 = cr0 - th, ix0 = cc0_ - tw;
        ok0[tt] = v0 && iy0 >= 0 && iy0 < HX && ix0 >= 0 && ix0 < HX;
        io0[tt] = iy0 * HX + ix0;
        int iy1 = cr1 - th, ix1 = cc1_ - tw;
        ok1[tt] = v1 && iy1 >= 0 && iy1 < HX && ix1 >= 0 && ix1 < HX;
        io1[tt] = iy1 * HX + ix1;
    }

    ull accA[8], accB[8];
    #pragma unroll
    for (int i = 0; i < 8; i++) { accA[i] = 0ull; accB[i] = 0ull; }

    const float* xb = x + (size_t)b * CX * HX * HX;

    for (int cc = 0; cc < CX; cc += 32) {
        __syncthreads();
        for (int i = tid; i < 16*32*NT; i += 256) {
            int tt = i % NT;
            int ci = (i / NT) & 31;
            int co = i / (NT * 32);
            int th = tt / NTW, tw = tt % NTW;
            int kh = (NTH == 2) ? 2*th : 1;
            int kw = (NTW == 2) ? 2*tw : 1;
            ((float*)swt)[((ci*8 + (co>>1))*NT + tt)*2 + (co&1)] =
                Wt[((size_t)(co0 + co)*CX + cc + ci)*9 + kh*3 + kw];
        }
        __syncthreads();

        #pragma unroll 1
        for (int ci = 0; ci < 32; ci++) {
            const float* pl = xb + (size_t)(cc + ci) * (HX * HX);
            ull in0[NT], in1[NT];
            #pragma unroll
            for (int tt = 0; tt < NT; tt++) {
                float a  = ok0[tt] ? __ldg(pl + io0[tt]) : 0.f;
                float bb = ok1[tt] ? __ldg(pl + io1[tt]) : 0.f;
                in0[tt] = bcast2(a);
                in1[tt] = bcast2(bb);
            }
            const ull* wbase = swt + ci * 8 * NT;
            #pragma unroll
            for (int cop = 0; cop < 8; cop++) {
                ull w[NT];
                if constexpr (NT == 4) {
                    const ulonglong2* q = (const ulonglong2*)(wbase + cop*4);
                    ulonglong2 q0 = q[0], q1 = q[1];
                    w[0] = q0.x; w[1] = q0.y; w[2] = q1.x; w[3] = q1.y;
                } else if constexpr (NT == 2) {
                    ulonglong2 q0 = ((const ulonglong2*)(wbase + cop*2))[0];
                    w[0] = q0.x; w[1] = q0.y;
                } else {
                    w[0] = wbase[cop];
                }
                ull a = accA[cop], bb2 = accB[cop];
                #pragma unroll
                for (int tt = 0; tt < NT; tt++) {
                    a   = fma2(w[tt], in0[tt], a);
                    bb2 = fma2(w[tt], in1[tt], bb2);
                }
                accA[cop] = a; accB[cop] = bb2;
            }
        }
    }

    const int oy0 = 2*cr0 + PY, ox0 = 2*cc0_ + PXP;
    const int oy1 = 2*cr1 + PY, ox1 = 2*cc1_ + PXP;
    #pragma unroll
    for (int cop = 0; cop < 8; cop++) {
        float a0, a1, b0, b1;
        unpack2(accA[cop], a0, a1);
        unpack2(accB[cop], b0, b1);
        int coA = co0 + 2*cop, coB = coA + 1;
        float bA = __ldg(bt + coA), bB = __ldg(bt + coB);
        if (v0) {
            g_h[((size_t)b*CX + coA)*NPIX + oy0*HY + ox0] = fmaxf(a0 + bA, 0.f);
            g_h[((size_t)b*CX + coB)*NPIX + oy0*HY + ox0] = fmaxf(a1 + bB, 0.f);
        }
        if (v1) {
            g_h[((size_t)b*CX + coA)*NPIX + oy1*HY + ox1] = fmaxf(b0 + bA, 0.f);
            g_h[((size_t)b*CX + coB)*NPIX + oy1*HY + ox1] = fmaxf(b1 + bB, 0.f);
        }
    }
}

__global__ void __launch_bounds__(256, 2) convt_all(
    const float* __restrict__ x, const float* __restrict__ Wt,
    const float* __restrict__ bt)
{
    __shared__ __align__(16) ull swt[32 * 8 * 4];   // max NT=4: 8 KB
    const int b   = blockIdx.z >> 2;
    const int cls = blockIdx.z & 3;
    const int co0 = blockIdx.y * 16;
    const int tid = threadIdx.x;
    const int bx  = blockIdx.x;
    switch (cls) {
        case 0: convt_body<2,2>(x, Wt, bt, swt, b, co0, bx, tid); break;
        case 1: convt_body<2,1>(x, Wt, bt, swt, b, co0, bx, tid); break;
        case 2: convt_body<1,2>(x, Wt, bt, swt, b, co0, bx, tid); break;
        default: convt_body<1,1>(x, Wt, bt, swt, b, co0, bx, tid); break;
    }
}

// ---------------- BN (batch stats) + ReLU ----------------
__global__ void bn_relu_kernel(const float* __restrict__ t,
                               const float* __restrict__ stats,
                               const float* __restrict__ gamma,
                               const float* __restrict__ beta,
                               float* __restrict__ out, int total) {
    int i = blockIdx.x * blockDim.x + threadIdx.x;
    if (i >= total) return;
    int c = (i / NPIX) % CG;
    float m   = stats[2 * c] * (1.f / NBHW);
    float var = stats[2 * c + 1] * (1.f / NBHW) - m * m;
    float sc  = gamma[c] * rsqrtf(fmaxf(var, 0.f) + EPSB);
    out[i] = fmaxf(sc * (t[i] - m) + beta[c], 0.f);
}

// ---------------- fused gate: depthwise Q + softmax over KD keys ------------
__global__ void gate_kernel(const float* __restrict__ y,
                            const float* __restrict__ Wq,
                            const float* __restrict__ bq,
                            const float* __restrict__ Wv,
                            const float* __restrict__ bv) {
    __shared__ float swv[KD], sbv[KD];
    int tid = threadIdx.y * 32 + threadIdx.x;
    if (tid < KD) { swv[tid] = Wv[tid]; sbv[tid] = bv[tid]; }
    __syncthreads();

    int zc = blockIdx.z;
    int c  = zc % CG;
    int b  = zc / CG;
    int ox = blockIdx.x * 32 + threadIdx.x;
    int oy = blockIdx.y * 8  + threadIdx.y;
    if (ox >= HY || oy >= HY) return;
    int pix = oy * HY + ox;

    // depthwise 3x3 Q at this pixel
    const float* p = y + ((size_t)b * CG + c) * NPIX;
    float qv = __ldg(bq + c);
    #pragma unroll
    for (int ky = 0; ky < 3; ky++) {
        int iy = oy + ky - 1;
        if (iy < 0 || iy >= HY) continue;
        #pragma unroll
        for (int kx = 0; kx < 3; kx++) {
            int ix = ox + kx - 1;
            if (ix < 0 || ix >= HY) continue;
            qv += __ldg(p + iy * HY + ix) * __ldg(Wq + c * 9 + ky * 3 + kx);
        }
    }
    qv = fmaxf(qv, 0.f);

    float yv = __ldg(p + pix);
    const float* kp = g_k + (size_t)b * KD * NPIX + pix;

    float s[KD];
    float mx = -1e30f;
    #pragma unroll
    for (int d = 0; d < KD; d++) {
        s[d] = qv * __ldg(kp + d * NPIX);
        mx = fmaxf(mx, s[d]);
    }
    float se = 0.f, num = 0.f;
    #pragma unroll
    for (int d = 0; d < KD; d++) {
        float e = expf(s[d] - mx);
        se  += e;
        num += e * fmaxf(yv * swv[d] + sbv[d], 0.f);
    }
    g_g[((size_t)b * CG + c) * NPIX + pix] = num / se;
}

// ---------------- host launch -----------------------------------------------
extern "C" void kernel_launch(void* const* d_in, const int* in_sizes, int n_in,
                              void* d_out, int out_size) {
    const float* x  = (const float*)d_in[0];
    const float* y  = (const float*)d_in[1];
    const float* Wt = (const float*)d_in[2];
    const float* bt = (const float*)d_in[3];
    const float* W1 = (const float*)d_in[4];
    const float* g1 = (const float*)d_in[5];
    const float* b1 = (const float*)d_in[6];
    const float* W2 = (const float*)d_in[7];
    const float* g2 = (const float*)d_in[8];
    const float* b2 = (const float*)d_in[9];
    const float* Wq = (const float*)d_in[10];
    const float* bq = (const float*)d_in[11];
    const float* Wk = (const float*)d_in[12];
    const float* bk = (const float*)d_in[13];
    const float* Wv = (const float*)d_in[14];
    const float* bv = (const float*)d_in[15];
    const float* W3 = (const float*)d_in[16];
    const float* g3 = (const float*)d_in[17];
    const float* b3 = (const float*)d_in[18];
    const float* W4 = (const float*)d_in[19];
    const float* g4 = (const float*)d_in[20];
    const float* b4 = (const float*)d_in[21];
    float* out = (float*)d_out;

    float *p_h, *p_tmp, *p_a, *p_xu, *p_k, *p_g, *p_o1, *p_stats;
    cudaGetSymbolAddress((void**)&p_h,     g_h);
    cudaGetSymbolAddress((void**)&p_tmp,   g_tmp);
    cudaGetSymbolAddress((void**)&p_a,     g_a);
    cudaGetSymbolAddress((void**)&p_xu,    g_xu);
    cudaGetSymbolAddress((void**)&p_k,     g_k);
    cudaGetSymbolAddress((void**)&p_g,     g_g);
    cudaGetSymbolAddress((void**)&p_o1,    g_o1);
    cudaGetSymbolAddress((void**)&p_stats, g_stats);

    dim3 grdCG(5, CG/8, BB);   // conv3x3_v2 for 128-out convs: 320 blocks
    dim3 grdK (5, KD/8, BB);   // 32-out conv: 80 blocks
    int  elems = BB * CG * NPIX;
    int  eb = (elems + 255) / 256;

    zero_stats_kernel<<<1, 1024>>>();

    // ConvTranspose + bias + relu: all parity classes in one launch (768 blocks)
    convt_all<<<dim3(3, CX/16, BB*4), 256>>>(x, Wt, bt);

    // DoubleConv(256 -> 128)
    conv3x3_v2<CX, false, true, false><<<grdCG, 256>>>(p_h, W1, nullptr, p_tmp, p_stats + 0, CG);
    bn_relu_kernel<<<eb, 256>>>(p_tmp, p_stats + 0, g1, b1, p_a, elems);
    conv3x3_v2<CG, false, true, false><<<grdCG, 256>>>(p_a, W2, nullptr, p_tmp, p_stats + 2*CG, CG);
    bn_relu_kernel<<<eb, 256>>>(p_tmp, p_stats + 2*CG, g2, b2, p_xu, elems);

    // Gate: K conv then fused Q+softmax gate
    conv3x3_v2<CG, true, false, true><<<grdK, 256>>>(p_xu, Wk, bk, p_k, nullptr, KD);
    gate_kernel<<<dim3(3, 9, BB*CG), dim3(32, 8)>>>(y, Wq, bq, Wv, bv);

    // final DoubleConv(128 -> 128)
    conv3x3_v2<CG, false, true, false><<<grdCG, 256>>>(p_g, W3, nullptr, p_tmp, p_stats + 4*CG, CG);
    bn_relu_kernel<<<eb, 256>>>(p_tmp, p_stats + 4*CG, g3, b3, p_o1, elems);
    conv3x3_v2<CG, false, true, false><<<grdCG, 256>>>(p_o1, W4, nullptr, p_tmp, p_stats + 6*CG, CG);
    bn_relu_kernel<<<eb, 256>>>(p_tmp, p_stats + 6*CG, g4, b4, out, elems);
}

// round 5
// speedup vs baseline: 1.1394x; 1.1394x over previous
#include <cuda_runtime.h>
#include <math.h>

// ---------------- problem constants ----------------
#define BB   4
#define CX   256
#define HX   32
#define HY   65
#define NPIX (HY*HY)   // 4225
#define CG   128
#define KD   32
#define NBHW 16900.0f
#define EPSB 1e-5f
#define PAIRS ((NPIX + 1) / 2)   // 2113

typedef unsigned long long ull;

// ---------------- packed f32x2 helpers ----------------
__device__ __forceinline__ ull pack2(float a, float b) {
    ull r; asm("mov.b64 %0, {%1,%2};" : "=l"(r) : "f"(a), "f"(b)); return r;
}
__device__ __forceinline__ ull bcast2(float a) { return pack2(a, a); }
__device__ __forceinline__ void unpack2(ull v, float& a, float& b) {
    asm("mov.b64 {%0,%1}, %2;" : "=f"(a), "=f"(b) : "l"(v));
}
__device__ __forceinline__ ull fma2(ull a, ull b, ull c) {
    ull d; asm("fma.rn.f32x2 %0, %1, %2, %3;" : "=l"(d) : "l"(a), "l"(b), "l"(c)); return d;
}

// ---------------- scratch ----------------
__device__ float g_h  [BB*CX*NPIX];
__device__ float g_tmp[BB*CG*NPIX];
__device__ float g_a  [BB*CG*NPIX];
__device__ float g_xu [BB*CG*NPIX];
__device__ float g_k  [BB*KD*NPIX];
__device__ float g_g  [BB*CG*NPIX];
__device__ float g_o1 [BB*CG*NPIX];
__device__ float g_stats[4*2*CG];

__global__ void zero_stats_kernel() {
    int i = threadIdx.x + blockIdx.x * blockDim.x;
    if (i < 4*2*CG) g_stats[i] = 0.f;
}

// =====================================================================
// conv3x3 (R3-proven tiling): thread = 2 flattened pixels x 16 co.
// =====================================================================
template<int CIN, bool HAS_BIAS, bool DO_STATS, bool DO_RELU>
__global__ void __launch_bounds__(256, 2) conv3x3_reg(
    const float* __restrict__ in, const float* __restrict__ W,
    const float* __restrict__ bias, float* __restrict__ out,
    float* __restrict__ stats, int Cout)
{
    const int b   = blockIdx.z;
    const int co0 = blockIdx.y * 16;
    const int tid = threadIdx.x;
    const int pair = blockIdx.x * 256 + tid;
    const int p0 = pair * 2, p1 = p0 + 1;
    const bool v0 = p0 < NPIX, v1 = p1 < NPIX;
    const int r0 = v0 ? p0 / HY : 0, c0 = v0 ? p0 % HY : 0;
    const int r1 = v1 ? p1 / HY : 0, c1 = v1 ? p1 % HY : 0;

    bool ok0[9], ok1[9];
    {
        bool u = r0 > 0, d = r0 < HY-1, l = c0 > 0, rr = c0 < HY-1;
        ok0[0]=v0&&u&&l; ok0[1]=v0&&u; ok0[2]=v0&&u&&rr;
        ok0[3]=v0&&l;    ok0[4]=v0;    ok0[5]=v0&&rr;
        ok0[6]=v0&&d&&l; ok0[7]=v0&&d; ok0[8]=v0&&d&&rr;
    }
    {
        bool u = r1 > 0, d = r1 < HY-1, l = c1 > 0, rr = c1 < HY-1;
        ok1[0]=v1&&u&&l; ok1[1]=v1&&u; ok1[2]=v1&&u&&rr;
        ok1[3]=v1&&l;    ok1[4]=v1;    ok1[5]=v1&&rr;
        ok1[6]=v1&&d&&l; ok1[7]=v1&&d; ok1[8]=v1&&d&&rr;
    }
    const int off[9] = {-HY-1, -HY, -HY+1, -1, 0, 1, HY-1, HY, HY+1};

    // [ci(32)][cop(8)][tap(10 pad)][pair(2)] floats = 20 KB
    __shared__ __align__(16) float sw[32 * 8 * 20];

    ull accA[8], accB[8];
    #pragma unroll
    for (int i = 0; i < 8; i++) { accA[i] = 0ull; accB[i] = 0ull; }

    const float* inb = in + (size_t)b * CIN * NPIX;

    for (int cc = 0; cc < CIN; cc += 32) {
        __syncthreads();
        for (int i = tid; i < 16*32*9; i += 256) {
            int t  = i % 9;
            int ci = (i / 9) & 31;
            int co = i / 288;
            sw[((ci*8 + (co>>1))*10 + t)*2 + (co&1)] =
                W[((size_t)(co0 + co)*CIN + cc + ci)*9 + t];
        }
        __syncthreads();

        #pragma unroll 1
        for (int ci = 0; ci < 32; ci++) {
            const float* pl = inb + (size_t)(cc + ci) * NPIX;
            ull in0[9], in1[9];
            #pragma unroll
            for (int t = 0; t < 9; t++) {
                float a  = ok0[t] ? __ldg(pl + p0 + off[t]) : 0.f;
                float bb = ok1[t] ? __ldg(pl + p1 + off[t]) : 0.f;
                in0[t] = bcast2(a);
                in1[t] = bcast2(bb);
            }
            const ulonglong2* wq = (const ulonglong2*)(sw + ci * 160);
            #pragma unroll
            for (int cop = 0; cop < 8; cop++) {
                ulonglong2 q0 = wq[cop*5+0], q1 = wq[cop*5+1], q2 = wq[cop*5+2],
                           q3 = wq[cop*5+3], q4 = wq[cop*5+4];
                ull w[9] = {q0.x, q0.y, q1.x, q1.y, q2.x, q2.y, q3.x, q3.y, q4.x};
                ull a = accA[cop], bb2 = accB[cop];
                #pragma unroll
                for (int t = 0; t < 9; t++) {
                    a   = fma2(w[t], in0[t], a);
                    bb2 = fma2(w[t], in1[t], bb2);
                }
                accA[cop] = a; accB[cop] = bb2;
            }
        }
    }

    // -------- epilogue --------
    #pragma unroll
    for (int cop = 0; cop < 8; cop++) {
        float a0, a1, b0, b1;
        unpack2(accA[cop], a0, a1);
        unpack2(accB[cop], b0, b1);
        int coA = co0 + 2*cop, coB = coA + 1;

        float oA0 = a0, oA1 = b0, oB0 = a1, oB1 = b1;
        if (HAS_BIAS) {
            float bA = __ldg(bias + coA), bB = __ldg(bias + coB);
            oA0 += bA; oA1 += bA; oB0 += bB; oB1 += bB;
        }
        if (DO_RELU) {
            oA0 = fmaxf(oA0, 0.f); oA1 = fmaxf(oA1, 0.f);
            oB0 = fmaxf(oB0, 0.f); oB1 = fmaxf(oB1, 0.f);
        }
        if (v0) {
            out[((size_t)b*Cout + coA)*NPIX + p0] = oA0;
            out[((size_t)b*Cout + coB)*NPIX + p0] = oB0;
        }
        if (v1) {
            out[((size_t)b*Cout + coA)*NPIX + p1] = oA1;
            out[((size_t)b*Cout + coB)*NPIX + p1] = oB1;
        }
        if (DO_STATS) {
            float sA = a0 + b0, qA = a0*a0 + b0*b0;
            float sB = a1 + b1, qB = a1*a1 + b1*b1;
            #pragma unroll
            for (int o = 16; o > 0; o >>= 1) {
                sA += __shfl_down_sync(0xffffffffu, sA, o);
                qA += __shfl_down_sync(0xffffffffu, qA, o);
                sB += __shfl_down_sync(0xffffffffu, sB, o);
                qB += __shfl_down_sync(0xffffffffu, qB, o);
            }
            if ((tid & 31) == 0) {
                atomicAdd(&stats[2*coA],     sA);
                atomicAdd(&stats[2*coA + 1], qA);
                atomicAdd(&stats[2*coB],     sB);
                atomicAdd(&stats[2*coB + 1], qB);
            }
        }
    }
}

// =====================================================================
// ConvTranspose: all 4 parity classes in ONE kernel (z = b*4 + class).
// =====================================================================
template<int NTH, int NTW>
__device__ __forceinline__ void convt_body(
    const float* __restrict__ x, const float* __restrict__ Wt,
    const float* __restrict__ bt, ull* swt, int b, int co0, int bx, int tid)
{
    constexpr int NT  = NTH * NTW;
    constexpr int PY  = (NTH == 2) ? 0 : 1;
    constexpr int PXP = (NTW == 2) ? 0 : 1;
    constexpr int CXN = (PXP == 0) ? 33 : 32;
    constexpr int RY  = (PY  == 0) ? 33 : 32;
    constexpr int NPC = RY * CXN;

    if (bx * 256 >= (NPC + 1) / 2) return;   // block-uniform early-out

    const int pair = bx * 256 + tid;
    const int p0 = pair*2, p1 = p0 + 1;
    const bool v0 = p0 < NPC, v1 = p1 < NPC;
    const int cr0 = v0 ? p0 / CXN : 0, cc0_ = v0 ? p0 % CXN : 0;
    const int cr1 = v1 ? p1 / CXN : 0, cc1_ = v1 ? p1 % CXN : 0;

    bool ok0[NT], ok1[NT];
    int  io0[NT], io1[NT];
    #pragma unroll
    for (int tt = 0; tt < NT; tt++) {
        int th = tt / NTW, tw = tt % NTW;
        int iy0 = cr0 - th, ix0 = cc0_ - tw;
        ok0[tt] = v0 && iy0 >= 0 && iy0 < HX && ix0 >= 0 && ix0 < HX;
        io0[tt] = iy0 * HX + ix0;
        int iy1 = cr1 - th, ix1 = cc1_ - tw;
        ok1[tt] = v1 && iy1 >= 0 && iy1 < HX && ix1 >= 0 && ix1 < HX;
        io1[tt] = iy1 * HX + ix1;
    }

    ull accA[8], accB[8];
    #pragma unroll
    for (int i = 0; i < 8; i++) { accA[i] = 0ull; accB[i] = 0ull; }

    const float* xb = x + (size_t)b * CX * HX * HX;

    for (int cc = 0; cc < CX; cc += 32) {
        __syncthreads();
        for (int i = tid; i < 16*32*NT; i += 256) {
            int tt = i % NT;
            int ci = (i / NT) & 31;
            int co = i / (NT * 32);
            int th = tt / NTW, tw = tt % NTW;
            int kh = (NTH == 2) ? 2*th : 1;
            int kw = (NTW == 2) ? 2*tw : 1;
            ((float*)swt)[((ci*8 + (co>>1))*NT + tt)*2 + (co&1)] =
                Wt[((size_t)(co0 + co)*CX + cc + ci)*9 + kh*3 + kw];
        }
        __syncthreads();

        #pragma unroll 1
        for (int ci = 0; ci < 32; ci++) {
            const float* pl = xb + (size_t)(cc + ci) * (HX * HX);
            ull in0[NT], in1[NT];
            #pragma unroll
            for (int tt = 0; tt < NT; tt++) {
                float a  = ok0[tt] ? __ldg(pl + io0[tt]) : 0.f;
                float bb = ok1[tt] ? __ldg(pl + io1[tt]) : 0.f;
                in0[tt] = bcast2(a);
                in1[tt] = bcast2(bb);
            }
            const ull* wbase = swt + ci * 8 * NT;
            #pragma unroll
            for (int cop = 0; cop < 8; cop++) {
                ull w[NT];
                if constexpr (NT == 4) {
                    const ulonglong2* q = (const ulonglong2*)(wbase + cop*4);
                    ulonglong2 q0 = q[0], q1 = q[1];
                    w[0] = q0.x; w[1] = q0.y; w[2] = q1.x; w[3] = q1.y;
                } else if constexpr (NT == 2) {
                    ulonglong2 q0 = ((const ulonglong2*)(wbase + cop*2))[0];
                    w[0] = q0.x; w[1] = q0.y;
                } else {
                    w[0] = wbase[cop];
                }
                ull a = accA[cop], bb2 = accB[cop];
                #pragma unroll
                for (int tt = 0; tt < NT; tt++) {
                    a   = fma2(w[tt], in0[tt], a);
                    bb2 = fma2(w[tt], in1[tt], bb2);
                }
                accA[cop] = a; accB[cop] = bb2;
            }
        }
    }

    const int oy0 = 2*cr0 + PY, ox0 = 2*cc0_ + PXP;
    const int oy1 = 2*cr1 + PY, ox1 = 2*cc1_ + PXP;
    #pragma unroll
    for (int cop = 0; cop < 8; cop++) {
        float a0, a1, b0, b1;
        unpack2(accA[cop], a0, a1);
        unpack2(accB[cop], b0, b1);
        int coA = co0 + 2*cop, coB = coA + 1;
        float bA = __ldg(bt + coA), bB = __ldg(bt + coB);
        if (v0) {
            g_h[((size_t)b*CX + coA)*NPIX + oy0*HY + ox0] = fmaxf(a0 + bA, 0.f);
            g_h[((size_t)b*CX + coB)*NPIX + oy0*HY + ox0] = fmaxf(a1 + bB, 0.f);
        }
        if (v1) {
            g_h[((size_t)b*CX + coA)*NPIX + oy1*HY + ox1] = fmaxf(b0 + bA, 0.f);
            g_h[((size_t)b*CX + coB)*NPIX + oy1*HY + ox1] = fmaxf(b1 + bB, 0.f);
        }
    }
}

__global__ void __launch_bounds__(256, 2) convt_all(
    const float* __restrict__ x, const float* __restrict__ Wt,
    const float* __restrict__ bt)
{
    __shared__ __align__(16) ull swt[32 * 8 * 4];   // max NT=4: 8 KB
    const int b   = blockIdx.z >> 2;
    const int cls = blockIdx.z & 3;
    const int co0 = blockIdx.y * 16;
    const int tid = threadIdx.x;
    const int bx  = blockIdx.x;
    switch (cls) {
        case 0: convt_body<2,2>(x, Wt, bt, swt, b, co0, bx, tid); break;
        case 1: convt_body<2,1>(x, Wt, bt, swt, b, co0, bx, tid); break;
        case 2: convt_body<1,2>(x, Wt, bt, swt, b, co0, bx, tid); break;
        default: convt_body<1,1>(x, Wt, bt, swt, b, co0, bx, tid); break;
    }
}

// ---------------- BN (batch stats) + ReLU ----------------
__global__ void bn_relu_kernel(const float* __restrict__ t,
                               const float* __restrict__ stats,
                               const float* __restrict__ gamma,
                               const float* __restrict__ beta,
                               float* __restrict__ out, int total) {
    int i = blockIdx.x * blockDim.x + threadIdx.x;
    if (i >= total) return;
    int c = (i / NPIX) % CG;
    float m   = stats[2 * c] * (1.f / NBHW);
    float var = stats[2 * c + 1] * (1.f / NBHW) - m * m;
    float sc  = gamma[c] * rsqrtf(fmaxf(var, 0.f) + EPSB);
    out[i] = fmaxf(sc * (t[i] - m) + beta[c], 0.f);
}

// ---------------- fused gate: depthwise Q + softmax over KD keys ------------
__global__ void gate_kernel(const float* __restrict__ y,
                            const float* __restrict__ Wq,
                            const float* __restrict__ bq,
                            const float* __restrict__ Wv,
                            const float* __restrict__ bv) {
    __shared__ float swv[KD], sbv[KD];
    int tid = threadIdx.y * 32 + threadIdx.x;
    if (tid < KD) { swv[tid] = Wv[tid]; sbv[tid] = bv[tid]; }
    __syncthreads();

    int zc = blockIdx.z;
    int c  = zc % CG;
    int b  = zc / CG;
    int ox = blockIdx.x * 32 + threadIdx.x;
    int oy = blockIdx.y * 8  + threadIdx.y;
    if (ox >= HY || oy >= HY) return;
    int pix = oy * HY + ox;

    const float* p = y + ((size_t)b * CG + c) * NPIX;
    float qv = __ldg(bq + c);
    #pragma unroll
    for (int ky = 0; ky < 3; ky++) {
        int iy = oy + ky - 1;
        if (iy < 0 || iy >= HY) continue;
        #pragma unroll
        for (int kx = 0; kx < 3; kx++) {
            int ix = ox + kx - 1;
            if (ix < 0 || ix >= HY) continue;
            qv += __ldg(p + iy * HY + ix) * __ldg(Wq + c * 9 + ky * 3 + kx);
        }
    }
    qv = fmaxf(qv, 0.f);

    float yv = __ldg(p + pix);
    const float* kp = g_k + (size_t)b * KD * NPIX + pix;

    float s[KD];
    float mx = -1e30f;
    #pragma unroll
    for (int d = 0; d < KD; d++) {
        s[d] = qv * __ldg(kp + d * NPIX);
        mx = fmaxf(mx, s[d]);
    }
    float se = 0.f, num = 0.f;
    #pragma unroll
    for (int d = 0; d < KD; d++) {
        float e = expf(s[d] - mx);
        se  += e;
        num += e * fmaxf(yv * swv[d] + sbv[d], 0.f);
    }
    g_g[((size_t)b * CG + c) * NPIX + pix] = num / se;
}

// ---------------- host launch -----------------------------------------------
extern "C" void kernel_launch(void* const* d_in, const int* in_sizes, int n_in,
                              void* d_out, int out_size) {
    const float* x  = (const float*)d_in[0];
    const float* y  = (const float*)d_in[1];
    const float* Wt = (const float*)d_in[2];
    const float* bt = (const float*)d_in[3];
    const float* W1 = (const float*)d_in[4];
    const float* g1 = (const float*)d_in[5];
    const float* b1 = (const float*)d_in[6];
    const float* W2 = (const float*)d_in[7];
    const float* g2 = (const float*)d_in[8];
    const float* b2 = (const float*)d_in[9];
    const float* Wq = (const float*)d_in[10];
    const float* bq = (const float*)d_in[11];
    const float* Wk = (const float*)d_in[12];
    const float* bk = (const float*)d_in[13];
    const float* Wv = (const float*)d_in[14];
    const float* bv = (const float*)d_in[15];
    const float* W3 = (const float*)d_in[16];
    const float* g3 = (const float*)d_in[17];
    const float* b3 = (const float*)d_in[18];
    const float* W4 = (const float*)d_in[19];
    const float* g4 = (const float*)d_in[20];
    const float* b4 = (const float*)d_in[21];
    float* out = (float*)d_out;

    float *p_h, *p_tmp, *p_a, *p_xu, *p_k, *p_g, *p_o1, *p_stats;
    cudaGetSymbolAddress((void**)&p_h,     g_h);
    cudaGetSymbolAddress((void**)&p_tmp,   g_tmp);
    cudaGetSymbolAddress((void**)&p_a,     g_a);
    cudaGetSymbolAddress((void**)&p_xu,    g_xu);
    cudaGetSymbolAddress((void**)&p_k,     g_k);
    cudaGetSymbolAddress((void**)&p_g,     g_g);
    cudaGetSymbolAddress((void**)&p_o1,    g_o1);
    cudaGetSymbolAddress((void**)&p_stats, g_stats);

    const int BX = (PAIRS + 255) / 256;   // 9
    dim3 grdCG(BX, CG/16, BB);            // 128-out convs: 288 blocks
    dim3 grdK (BX, KD/16, BB);            // 32-out conv: 72 blocks
    int  elems = BB * CG * NPIX;
    int  eb = (elems + 255) / 256;

    zero_stats_kernel<<<1, 1024>>>();

    // ConvTranspose + bias + relu: all parity classes, one launch (768 blocks)
    convt_all<<<dim3(3, CX/16, BB*4), 256>>>(x, Wt, bt);

    // DoubleConv(256 -> 128)
    conv3x3_reg<CX, false, true, false><<<grdCG, 256>>>(p_h, W1, nullptr, p_tmp, p_stats + 0, CG);
    bn_relu_kernel<<<eb, 256>>>(p_tmp, p_stats + 0, g1, b1, p_a, elems);
    conv3x3_reg<CG, false, true, false><<<grdCG, 256>>>(p_a, W2, nullptr, p_tmp, p_stats + 2*CG, CG);
    bn_relu_kernel<<<eb, 256>>>(p_tmp, p_stats + 2*CG, g2, b2, p_xu, elems);

    // Gate: K conv then fused Q+softmax gate
    conv3x3_reg<CG, true, false, true><<<grdK, 256>>>(p_xu, Wk, bk, p_k, nullptr, KD);
    gate_kernel<<<dim3(3, 9, BB*CG), dim3(32, 8)>>>(y, Wq, bq, Wv, bv);

    // final DoubleConv(128 -> 128)
    conv3x3_reg<CG, false, true, false><<<grdCG, 256>>>(p_g, W3, nullptr, p_tmp, p_stats + 4*CG, CG);
    bn_relu_kernel<<<eb, 256>>>(p_tmp, p_stats + 4*CG, g3, b3, p_o1, elems);
    conv3x3_reg<CG, false, true, false><<<grdCG, 256>>>(p_o1, W4, nullptr, p_tmp, p_stats + 6*CG, CG);
    bn_relu_kernel<<<eb, 256>>>(p_tmp, p_stats + 6*CG, g4, b4, out, elems);
}